// round 5
// baseline (speedup 1.0000x reference)
#include <cuda_runtime.h>
#include <cstdint>

// YOLOv7 head post-process — R5: 64-cell tile split into two pipelined 32-cell
// halves; store of half A overlaps load/compute of half B.
// Input:  [16, 255, 80, 80] fp32 (channel stride 6400)
// Output: [16, 19200, 85] fp32  (85 contiguous per cell)

#define NA      3
#define CH      85
#define HW      6400
#define WW      80
#define CELLS   64
#define HCELLS  32
#define THREADS 256
#define HVEC    (CH * (HCELLS / 4))   // 680 float4 per half
#define STRIDE  8.0f

__device__ __forceinline__ float fsigmoid(float x) {
    float y;
    asm("tanh.approx.f32 %0, %1;" : "=f"(y) : "f"(0.5f * x));
    return fmaf(0.5f, y, 0.5f);
}

__device__ __forceinline__ void bulk_store(const float* smem_src, float* gdst, int bytes) {
    asm volatile("fence.proxy.async.shared::cta;" ::: "memory");
    uint32_t saddr;
    asm("{ .reg .u64 t; cvta.to.shared.u64 t, %1; cvt.u32.u64 %0, t; }"
        : "=r"(saddr) : "l"(smem_src));
    asm volatile(
        "cp.async.bulk.global.shared::cta.bulk_group [%0], [%1], %2;"
        :: "l"((uint64_t)gdst), "r"(saddr), "r"(bytes) : "memory");
    asm volatile("cp.async.bulk.commit_group;" ::: "memory");
}

__device__ __forceinline__ void process_half(
        const float* __restrict__ ibh,   // input base for this half (already +cell offset)
        float* __restrict__ sh,          // smem half buffer [HCELLS*CH]
        int cell0,                       // global cell index of first cell in half
        float aw, float ah, int tid) {
    #pragma unroll 3
    for (int i = tid; i < HVEC; i += THREADS) {
        int c = i >> 3;                  // channel 0..84 (uniform per 8-lane octet)
        int q = i & 7;                   // float4 within 32-cell half-row
        float4 v = *(const float4*)(ibh + (size_t)c * HW + 4 * q);
        float vv[4] = {v.x, v.y, v.z, v.w};
        #pragma unroll
        for (int k = 0; k < 4; k++) {
            int cell = 4 * q + k;
            float x = vv[k], t;
            if (c >= 4) {
                t = fsigmoid(x);
            } else if (c == 0) {
                t = (fsigmoid(x) + (float)((cell0 + cell) % WW)) * STRIDE;
            } else if (c == 1) {
                t = (fsigmoid(x) + (float)((cell0 + cell) / WW)) * STRIDE;
            } else if (c == 2) {
                t = __expf(fminf(fmaxf(x, -16.0f), 16.0f)) * aw;
            } else {
                t = __expf(fminf(fmaxf(x, -16.0f), 16.0f)) * ah;
            }
            sh[cell * CH + c] = t;       // conflict-free scatter (stride 85)
        }
    }
}

__global__ __launch_bounds__(THREADS)
void yolo_head_kernel(const float* __restrict__ in,
                      const float* __restrict__ anchors,
                      float* __restrict__ out) {
    __shared__ __align__(16) float s[CELLS * CH];   // two 10,880B halves

    const int groups = HW / CELLS;    // 100
    int bid   = blockIdx.x;
    int group = bid % groups;
    int a     = (bid / groups) % NA;
    int b     = bid / (NA * groups);
    int pos0  = group * CELLS;
    int tid   = threadIdx.x;

    const float* ib = in + (size_t)(b * NA + a) * (CH * HW) + pos0;
    float* ob       = out + (size_t)((b * NA + a) * HW + pos0) * CH;
    float aw = anchors[2 * a + 0];
    float ah = anchors[2 * a + 1];

    // ---- half A: cells [pos0, pos0+32) ----
    process_half(ib, s, pos0, aw, ah, tid);
    __syncthreads();
    if (tid == 0)
        bulk_store(s, ob, HCELLS * CH * 4);          // async: drains during half B

    // ---- half B: cells [pos0+32, pos0+64) ----
    process_half(ib + HCELLS, s + HCELLS * CH, pos0 + HCELLS, aw, ah, tid);
    __syncthreads();
    if (tid == 0) {
        bulk_store(s + HCELLS * CH, ob + (size_t)HCELLS * CH, HCELLS * CH * 4);
        asm volatile("cp.async.bulk.wait_group 0;" ::: "memory");
    }
}

extern "C" void kernel_launch(void* const* d_in, const int* in_sizes, int n_in,
                              void* d_out, int out_size) {
    const float* in      = (const float*)d_in[0];
    const float* anchors = (const float*)d_in[1];
    float* out           = (float*)d_out;

    int grid = 16 * NA * (HW / CELLS);   // 4800 blocks
    yolo_head_kernel<<<grid, THREADS>>>(in, anchors, out);
}

// round 6
// speedup vs baseline: 1.1757x; 1.1757x over previous
#include <cuda_runtime.h>
#include <cstdint>

// YOLOv7 head post-process — R6: R4 structure + explicit 5-deep load staging.
// Input:  [16, 255, 80, 80] fp32 (channel stride 6400)
// Output: [16, 19200, 85] fp32  (85 contiguous per cell)
//
// Block (256 thr, 5 blocks/SM) = 64 cells x 85 channels (21,760 B contiguous out).
//   bulk loads : c=5..84 -> 1280 float4 = 5 LDG.128/thread, ALL issued before
//                any use (register-staged -> MLP_eff = 5)
//   special    : c=0..4  -> 80 float4, tid<80
//   drain      : ONE cp.async.bulk (21,760 B) per block

#define NA      3
#define CH      85
#define HW      6400
#define WW      80
#define CELLS   64
#define THREADS 256
#define STRIDE  8.0f

__device__ __forceinline__ float fsigmoid(float x) {
    float y;
    asm("tanh.approx.f32 %0, %1;" : "=f"(y) : "f"(0.5f * x));
    return fmaf(0.5f, y, 0.5f);
}

__global__ __launch_bounds__(THREADS, 5)
void yolo_head_kernel(const float* __restrict__ in,
                      const float* __restrict__ anchors,
                      float* __restrict__ out) {
    __shared__ __align__(16) float s[CELLS * CH];   // 21,760 B, output layout

    const int groups = HW / CELLS;    // 100
    int bid   = blockIdx.x;
    int group = bid % groups;
    int a     = (bid / groups) % NA;
    int b     = bid / (NA * groups);
    int pos0  = group * CELLS;
    int tid   = threadIdx.x;

    const float* ib = in + (size_t)(b * NA + a) * (CH * HW) + pos0;

    // ---- stage: issue all 5 bulk LDG.128 up front (independent -> MLP=5) ----
    float4 r[5];
    #pragma unroll
    for (int p = 0; p < 5; p++) {
        int i = p * THREADS + tid;           // 0..1279
        int c = 5 + (i >> 4);                // channel, uniform per 16-lane group
        int q = i & 15;                      // float4 index within 64-cell row
        r[p] = *(const float4*)(ib + (size_t)c * HW + 4 * q);
    }

    // ---- special channels 0..4 (80 float4): issue while bulk loads fly ----
    float4 vs;
    float aw = 0.f, ah = 0.f;
    if (tid < 80) {
        vs = *(const float4*)(ib + (size_t)(tid >> 4) * HW + 4 * (tid & 15));
        aw = anchors[2 * a + 0];
        ah = anchors[2 * a + 1];
    }

    // ---- compute + scatter bulk channels ----
    #pragma unroll
    for (int p = 0; p < 5; p++) {
        int i = p * THREADS + tid;
        int c = 5 + (i >> 4);
        int q = i & 15;
        float vv[4] = {r[p].x, r[p].y, r[p].z, r[p].w};
        #pragma unroll
        for (int k = 0; k < 4; k++)
            s[(4 * q + k) * CH + c] = fsigmoid(vv[k]);
    }

    // ---- compute + scatter special channels ----
    if (tid < 80) {
        int c = tid >> 4;
        int q = tid & 15;
        float vv[4] = {vs.x, vs.y, vs.z, vs.w};
        #pragma unroll
        for (int k = 0; k < 4; k++) {
            int cell = 4 * q + k;
            float x = vv[k], t;
            if (c == 0)      t = (fsigmoid(x) + (float)((pos0 + cell) % WW)) * STRIDE;
            else if (c == 1) t = (fsigmoid(x) + (float)((pos0 + cell) / WW)) * STRIDE;
            else if (c == 2) t = __expf(fminf(fmaxf(x, -16.0f), 16.0f)) * aw;
            else if (c == 3) t = __expf(fminf(fmaxf(x, -16.0f), 16.0f)) * ah;
            else             t = fsigmoid(x);
            s[cell * CH + c] = t;
        }
    }
    __syncthreads();

    // ---- drain: single TMA bulk store of the contiguous 64-cell tile ----
    if (tid == 0) {
        asm volatile("fence.proxy.async.shared::cta;" ::: "memory");
        uint32_t saddr;
        asm("{ .reg .u64 t; cvta.to.shared.u64 t, %1; cvt.u32.u64 %0, t; }"
            : "=r"(saddr) : "l"(s));
        uint64_t gaddr = (uint64_t)(out + (size_t)((b * NA + a) * HW + pos0) * CH);
        asm volatile(
            "cp.async.bulk.global.shared::cta.bulk_group [%0], [%1], %2;"
            :: "l"(gaddr), "r"(saddr), "n"(CELLS * CH * 4) : "memory");
        asm volatile("cp.async.bulk.commit_group;" ::: "memory");
        asm volatile("cp.async.bulk.wait_group 0;" ::: "memory");
    }
}

extern "C" void kernel_launch(void* const* d_in, const int* in_sizes, int n_in,
                              void* d_out, int out_size) {
    const float* in      = (const float*)d_in[0];
    const float* anchors = (const float*)d_in[1];
    float* out           = (float*)d_out;

    int grid = 16 * NA * (HW / CELLS);   // 4800 blocks
    yolo_head_kernel<<<grid, THREADS>>>(in, anchors, out);
}